// round 15
// baseline (speedup 1.0000x reference)
#include <cuda_runtime.h>
#include <cuda_bf16.h>

// GCN 2-layer + mean pool — padded-CSR pull mode, warp-aggregated pooling.
// Inputs: 0:x[100000,5] f32  1:edge_index[2,3.2M] i32  2:batch[100000] i32 (sorted)
//         3:W1[5,16] 4:b1[16] 5:W2[16,16] 6:b2[16]   Output: [512,16] f32
//
// Math: out_i = dinv_i * ( sum_{s->i} sfeat_s + sfeat_i ) + b, sfeat = dinv*feat.
// Padded CSR: node i's in-neighbors at g_eslot[i*128 .. i*128+g_pos[i]).
// Cross-run invariants (graph replay): g_pos zeroed per-node by k_pull2 after its
// last read, g_semaP self-resets, pool/cnt zeroed by k_init_scatter.

#define MAX_NODES  100000
#define MAX_GRAPHS 512
#define SLOT_LOG   7
#define SLOTS      128          // max in-degree supported (input max ~60)
#define PULL_BLK   128

__device__ float g_dinv[MAX_NODES];
__device__ __align__(16) float g_feat [MAX_NODES * 16]; // fp32 xW1 (pre-scale)
__device__ __align__(16) float g_sfeat[MAX_NODES * 16]; // dinv*(xW1)
__device__ __align__(16) float g_acc  [MAX_NODES * 16]; // dinv*(h1@W2)
__device__ float g_pool[MAX_GRAPHS * 16];
__device__ float g_cnt [MAX_GRAPHS];
__device__ int   g_pos  [MAX_NODES];          // degree counters (zero across runs)
__device__ __align__(16) int g_eslot[MAX_NODES * SLOTS];  // padded CSR, 51.2 MB
__device__ int   g_semaP;                     // static-zero, self-resetting

// ---------------------------------------------------------------- K0: init (feat=x@W1, zero pool) ∥ scatter
__global__ void k_init_scatter(const float* __restrict__ x,
                               const float* __restrict__ W1,
                               const int* __restrict__ src,
                               const int* __restrict__ dst,
                               int N, int G, int E, int nInitBlk) {
    if ((int)blockIdx.x < nInitBlk) {
        __shared__ float sW1[80];
        if (threadIdx.x < 80) sW1[threadIdx.x] = W1[threadIdx.x];
        __syncthreads();
        int t = blockIdx.x * 256 + threadIdx.x;
        if (t < G * 16) g_pool[t] = 0.f;
        if (t < G)      g_cnt[t]  = 0.f;
        if (t >= N * 16) return;
        int i = t >> 4, f = t & 15;
        float acc = 0.f;
#pragma unroll
        for (int k = 0; k < 5; k++)
            acc += __ldg(&x[i * 5 + k]) * sW1[k * 16 + f];
        g_feat[t] = acc;
    } else {
        int base = ((blockIdx.x - nInitBlk) * 256 + threadIdx.x) * 4;
        if (base + 3 < E) {
            int4 s = *reinterpret_cast<const int4*>(src + base);
            int4 d = *reinterpret_cast<const int4*>(dst + base);
            int p0 = atomicAdd(&g_pos[d.x], 1);
            int p1 = atomicAdd(&g_pos[d.y], 1);
            int p2 = atomicAdd(&g_pos[d.z], 1);
            int p3 = atomicAdd(&g_pos[d.w], 1);
            if (p0 < SLOTS) g_eslot[(d.x << SLOT_LOG) + p0] = s.x;
            if (p1 < SLOTS) g_eslot[(d.y << SLOT_LOG) + p1] = s.y;
            if (p2 < SLOTS) g_eslot[(d.z << SLOT_LOG) + p2] = s.z;
            if (p3 < SLOTS) g_eslot[(d.w << SLOT_LOG) + p3] = s.w;
        } else {
            for (int k = base; k < E; k++) {
                int d = dst[k];
                int p = atomicAdd(&g_pos[d], 1);
                if (p < SLOTS) g_eslot[(d << SLOT_LOG) + p] = src[k];
            }
        }
    }
}

// ---------------------------------------------------------------- K1: dinv from degree + prescale feat
__global__ void k_prescale(int N) {
    int t = blockIdx.x * 256 + threadIdx.x;
    int i = t >> 2;
    if (i >= N) return;
    int lane = t & 3;
    int deg = g_pos[i];
    float di = rsqrtf((float)(deg + 1));               // +1 = self loop
    if (lane == 0) g_dinv[i] = di;
    float4 v = ((const float4*)g_feat)[i * 4 + lane];
    v.x *= di; v.y *= di; v.z *= di; v.w *= di;
    ((float4*)g_sfeat)[i * 4 + lane] = v;
}

// ---------------------------------------------------------------- pull core: 4 thr/node, float4, unroll-8
// f4 holds PRE-SCALED features. Returns dinv_node * (sum_neighbors + self).
__device__ __forceinline__ float4 pull_node(int node, int lane,
                                            const float4* __restrict__ f4) {
    const int4* row4 = reinterpret_cast<const int4*>(&g_eslot[node << SLOT_LOG]);
    int end = min(g_pos[node], SLOTS);
    float4 a0 = make_float4(0.f, 0.f, 0.f, 0.f);
    float4 a1 = make_float4(0.f, 0.f, 0.f, 0.f);
    int j = 0;
    for (; j + 8 <= end; j += 8) {
        int4 ia = row4[(j >> 2) + 0];                  // LDG.128 index loads
        int4 ib = row4[(j >> 2) + 1];
        float4 v0 = f4[ia.x*4 + lane], v1 = f4[ia.y*4 + lane];
        float4 v2 = f4[ia.z*4 + lane], v3 = f4[ia.w*4 + lane];
        float4 v4 = f4[ib.x*4 + lane], v5 = f4[ib.y*4 + lane];
        float4 v6 = f4[ib.z*4 + lane], v7 = f4[ib.w*4 + lane];
        a0.x += v0.x + v1.x + v2.x + v3.x;  a1.x += v4.x + v5.x + v6.x + v7.x;
        a0.y += v0.y + v1.y + v2.y + v3.y;  a1.y += v4.y + v5.y + v6.y + v7.y;
        a0.z += v0.z + v1.z + v2.z + v3.z;  a1.z += v4.z + v5.z + v6.z + v7.z;
        a0.w += v0.w + v1.w + v2.w + v3.w;  a1.w += v4.w + v5.w + v6.w + v7.w;
    }
    const int* row = reinterpret_cast<const int*>(row4);
    for (; j < end; j++) {
        int s = row[j];
        float4 v = f4[s*4 + lane];
        a0.x += v.x; a0.y += v.y; a0.z += v.z; a0.w += v.w;
    }
    float4 sv = f4[node*4 + lane];                     // self (pre-scaled)
    float dd = g_dinv[node];
    return make_float4(dd*(a0.x + a1.x + sv.x), dd*(a0.y + a1.y + sv.y),
                       dd*(a0.z + a1.z + sv.z), dd*(a0.w + a1.w + sv.w));
}

// ---------------------------------------------------------------- K2: layer-1 pull + relu + @W2, prescaled out
__global__ void __launch_bounds__(PULL_BLK, 12)
k_pull1(const float* __restrict__ b1,
        const float* __restrict__ W2, int N) {
    __shared__ float sW2[256];
    __shared__ float sb1[16];
    if (threadIdx.x < 128) {
        sW2[threadIdx.x]       = W2[threadIdx.x];
        sW2[threadIdx.x + 128] = W2[threadIdx.x + 128];
    }
    if (threadIdx.x < 16)  sb1[threadIdx.x] = b1[threadIdx.x];
    __syncthreads();
    int t = blockIdx.x * PULL_BLK + threadIdx.x;
    int node = t >> 2;
    bool valid = node < N;
    int nodec = valid ? node : N - 1;                  // keep shfl groups intact
    int lane = t & 3;
    float4 r = pull_node(nodec, lane, (const float4*)g_sfeat);
    float4 h;
    h.x = fmaxf(r.x + sb1[lane*4+0], 0.f);
    h.y = fmaxf(r.y + sb1[lane*4+1], 0.f);
    h.z = fmaxf(r.z + sb1[lane*4+2], 0.f);
    h.w = fmaxf(r.w + sb1[lane*4+3], 0.f);
    float4 res = make_float4(0.f, 0.f, 0.f, 0.f);
    int fb = lane * 4;
#pragma unroll
    for (int g = 0; g < 4; g++) {
        float hx = __shfl_sync(0xffffffffu, h.x, g, 4);
        float hy = __shfl_sync(0xffffffffu, h.y, g, 4);
        float hz = __shfl_sync(0xffffffffu, h.z, g, 4);
        float hw = __shfl_sync(0xffffffffu, h.w, g, 4);
        int kb = g * 4;
        const float* w0 = &sW2[(kb+0)*16 + fb];
        const float* w1 = &sW2[(kb+1)*16 + fb];
        const float* w2 = &sW2[(kb+2)*16 + fb];
        const float* w3 = &sW2[(kb+3)*16 + fb];
        res.x += hx*w0[0] + hy*w1[0] + hz*w2[0] + hw*w3[0];
        res.y += hx*w0[1] + hy*w1[1] + hz*w2[1] + hw*w3[1];
        res.z += hx*w0[2] + hy*w1[2] + hz*w2[2] + hw*w3[2];
        res.w += hx*w0[3] + hy*w1[3] + hz*w2[3] + hw*w3[3];
    }
    if (valid) {
        float dd = g_dinv[node];                       // prescale for layer-2 pull
        res.x *= dd; res.y *= dd; res.z *= dd; res.w *= dd;
        ((float4*)g_acc)[node*4 + lane] = res;
    }
}

// ---------------------------------------------------------------- K3: layer-2 pull + relu + warp-agg pool + out
__global__ void __launch_bounds__(PULL_BLK, 12)
k_pull2(const int* __restrict__ batch,
        const float* __restrict__ b2,
        float* __restrict__ out, int N, int G, int nblk) {
    __shared__ int amLast;
    int t = blockIdx.x * PULL_BLK + threadIdx.x;
    int node = t >> 2;
    int lane = t & 3;
    float hx = 0.f, hy = 0.f, hz = 0.f, hw = 0.f;
    int g = -1;
    if (node < N) {
        int gb = batch[node];                          // hoisted: overlaps pull latency
        if ((unsigned)gb < (unsigned)G) g = gb;
        float4 r = pull_node(node, lane, (const float4*)g_acc);
        if (lane == 0) g_pos[node] = 0;                // reset for next run (after last read)
        float4 bv = __ldg(&((const float4*)b2)[lane]);
        hx = fmaxf(r.x + bv.x, 0.f);
        hy = fmaxf(r.y + bv.y, 0.f);
        hz = fmaxf(r.z + bv.z, 0.f);
        hw = fmaxf(r.w + bv.w, 0.f);
    }
    // batch is sorted: the warp's 8 nodes almost always share one graph.
    unsigned mask = 0xffffffffu;
    int g0 = __shfl_sync(mask, g, 0);
    bool uniform = __all_sync(mask, g == g0) && (g0 >= 0);
    if (uniform) {
        // reduce across the 8 node-groups (stride-4 lanes keep feature class)
#pragma unroll
        for (int off = 16; off >= 4; off >>= 1) {
            hx += __shfl_down_sync(mask, hx, off);
            hy += __shfl_down_sync(mask, hy, off);
            hz += __shfl_down_sync(mask, hz, off);
            hw += __shfl_down_sync(mask, hw, off);
        }
        int lid = threadIdx.x & 31;
        if (lid < 4) {
            float* p = &g_pool[g0 * 16 + lid * 4];
            atomicAdd(p + 0, hx);
            atomicAdd(p + 1, hy);
            atomicAdd(p + 2, hz);
            atomicAdd(p + 3, hw);
            if (lid == 0) atomicAdd(&g_cnt[g0], 8.0f);
        }
    } else if (g >= 0) {
        float* p = &g_pool[g * 16 + lane * 4];
        atomicAdd(p + 0, hx);
        atomicAdd(p + 1, hy);
        atomicAdd(p + 2, hz);
        atomicAdd(p + 3, hw);
        if (lane == 0) atomicAdd(&g_cnt[g], 1.0f);
    }
    __syncthreads();
    if (threadIdx.x == 0) {
        __threadfence();
        int old = atomicAdd(&g_semaP, 1);
        amLast = (old == nblk - 1);
    }
    __syncthreads();
    if (amLast) {
        __threadfence();
        for (int u = threadIdx.x; u < G * 16; u += PULL_BLK)
            out[u] = g_pool[u] / fmaxf(g_cnt[u >> 4], 1.0f);
        if (threadIdx.x == 0) g_semaP = 0;             // reset for next run
    }
}

// ----------------------------------------------------------------
extern "C" void kernel_launch(void* const* d_in, const int* in_sizes, int n_in,
                              void* d_out, int out_size) {
    const float* x     = (const float*)d_in[0];
    const int*   ei    = (const int*)d_in[1];
    const int*   batch = (const int*)d_in[2];
    const float* W1    = (const float*)d_in[3];
    const float* b1    = (const float*)d_in[4];
    const float* W2    = (const float*)d_in[5];
    const float* b2    = (const float*)d_in[6];
    float*       out   = (float*)d_out;

    int N = in_sizes[0] / 5;        // 100000
    int E = in_sizes[1] / 2;        // 3200000
    int G = out_size / 16;          // 512

    const int* src = ei;
    const int* dst = ei + E;

    int gN16 = (N * 16 + 255) / 256;                 // 6250 init blocks
    int gE4  = ((E + 3) / 4 + 255) / 256;            // 3125 scatter blocks
    int gN4p = (N * 4 + PULL_BLK - 1) / PULL_BLK;    // 3125 pull blocks (128 thr)
    int gN4  = (N * 4 + 255) / 256;                  // prescale blocks

    k_init_scatter<<<gN16 + gE4, 256>>>(x, W1, src, dst, N, G, E, gN16);
    k_prescale    <<<gN4,  256>>>(N);
    k_pull1       <<<gN4p, PULL_BLK>>>(b1, W2, N);
    k_pull2       <<<gN4p, PULL_BLK>>>(batch, b2, out, N, G, gN4p);
}

// round 16
// speedup vs baseline: 1.0835x; 1.0835x over previous
#include <cuda_runtime.h>
#include <cuda_bf16.h>

// GCN 2-layer + mean pool — padded-CSR pull mode, warp-aggregated pooling.
// Inputs: 0:x[100000,5] f32  1:edge_index[2,3.2M] i32  2:batch[100000] i32 (sorted)
//         3:W1[5,16] 4:b1[16] 5:W2[16,16] 6:b2[16]   Output: [512,16] f32
//
// Math: out_i = dinv_i * ( sum_{s->i} sfeat_s + sfeat_i ) + b, sfeat = dinv*feat.
// Padded CSR: node i's in-neighbors at g_eslot[i*128 .. i*128+g_pos[i]).
// Cross-run invariants (graph replay): g_pos zeroed per-node by k_pull2 after its
// last read, g_semaP self-resets, pool/cnt zeroed by k_init_scatter.

#define MAX_NODES  100000
#define MAX_GRAPHS 512
#define SLOT_LOG   7
#define SLOTS      128          // max in-degree supported (input max ~60)

__device__ float g_dinv[MAX_NODES];
__device__ __align__(16) float g_feat [MAX_NODES * 16]; // fp32 xW1 (pre-scale)
__device__ __align__(16) float g_sfeat[MAX_NODES * 16]; // dinv*(xW1)
__device__ __align__(16) float g_acc  [MAX_NODES * 16]; // dinv*(h1@W2)
__device__ float g_pool[MAX_GRAPHS * 16];
__device__ float g_cnt [MAX_GRAPHS];
__device__ int   g_pos  [MAX_NODES];          // degree counters (zero across runs)
__device__ __align__(16) int g_eslot[MAX_NODES * SLOTS];  // padded CSR, 51.2 MB
__device__ int   g_semaP;                     // static-zero, self-resetting

// ---------------------------------------------------------------- K0: init (feat=x@W1, zero pool) ∥ scatter
__global__ void k_init_scatter(const float* __restrict__ x,
                               const float* __restrict__ W1,
                               const int* __restrict__ src,
                               const int* __restrict__ dst,
                               int N, int G, int E, int nInitBlk) {
    if ((int)blockIdx.x < nInitBlk) {
        __shared__ float sW1[80];
        if (threadIdx.x < 80) sW1[threadIdx.x] = W1[threadIdx.x];
        __syncthreads();
        int t = blockIdx.x * 256 + threadIdx.x;
        if (t < G * 16) g_pool[t] = 0.f;
        if (t < G)      g_cnt[t]  = 0.f;
        if (t >= N * 16) return;
        int i = t >> 4, f = t & 15;
        float acc = 0.f;
#pragma unroll
        for (int k = 0; k < 5; k++)
            acc += __ldg(&x[i * 5 + k]) * sW1[k * 16 + f];
        g_feat[t] = acc;
    } else {
        int base = ((blockIdx.x - nInitBlk) * 256 + threadIdx.x) * 4;
        if (base + 3 < E) {
            int4 s = *reinterpret_cast<const int4*>(src + base);
            int4 d = *reinterpret_cast<const int4*>(dst + base);
            int p0 = atomicAdd(&g_pos[d.x], 1);
            int p1 = atomicAdd(&g_pos[d.y], 1);
            int p2 = atomicAdd(&g_pos[d.z], 1);
            int p3 = atomicAdd(&g_pos[d.w], 1);
            if (p0 < SLOTS) g_eslot[(d.x << SLOT_LOG) + p0] = s.x;
            if (p1 < SLOTS) g_eslot[(d.y << SLOT_LOG) + p1] = s.y;
            if (p2 < SLOTS) g_eslot[(d.z << SLOT_LOG) + p2] = s.z;
            if (p3 < SLOTS) g_eslot[(d.w << SLOT_LOG) + p3] = s.w;
        } else {
            for (int k = base; k < E; k++) {
                int d = dst[k];
                int p = atomicAdd(&g_pos[d], 1);
                if (p < SLOTS) g_eslot[(d << SLOT_LOG) + p] = src[k];
            }
        }
    }
}

// ---------------------------------------------------------------- K1: dinv from degree + prescale feat
__global__ void k_prescale(int N) {
    int t = blockIdx.x * 256 + threadIdx.x;
    int i = t >> 2;
    if (i >= N) return;
    int lane = t & 3;
    int deg = g_pos[i];
    float di = rsqrtf((float)(deg + 1));               // +1 = self loop
    if (lane == 0) g_dinv[i] = di;
    float4 v = ((const float4*)g_feat)[i * 4 + lane];
    v.x *= di; v.y *= di; v.z *= di; v.w *= di;
    ((float4*)g_sfeat)[i * 4 + lane] = v;
}

// ---------------------------------------------------------------- pull core: 4 thr/node, float4
// Tiers: unroll-8 main loop, unroll-4 tier, scalar tail (<=3 iters).
// f4 holds PRE-SCALED features. Returns dinv_node * (sum_neighbors + self).
__device__ __forceinline__ float4 pull_node(int node, int lane,
                                            const float4* __restrict__ f4) {
    const int4* row4 = reinterpret_cast<const int4*>(&g_eslot[node << SLOT_LOG]);
    int end = min(g_pos[node], SLOTS);
    float4 a0 = make_float4(0.f, 0.f, 0.f, 0.f);
    float4 a1 = make_float4(0.f, 0.f, 0.f, 0.f);
    int j = 0;
    for (; j + 8 <= end; j += 8) {
        int4 ia = row4[(j >> 2) + 0];                  // LDG.128 index loads
        int4 ib = row4[(j >> 2) + 1];
        float4 v0 = f4[ia.x*4 + lane], v1 = f4[ia.y*4 + lane];
        float4 v2 = f4[ia.z*4 + lane], v3 = f4[ia.w*4 + lane];
        float4 v4 = f4[ib.x*4 + lane], v5 = f4[ib.y*4 + lane];
        float4 v6 = f4[ib.z*4 + lane], v7 = f4[ib.w*4 + lane];
        a0.x += v0.x + v1.x + v2.x + v3.x;  a1.x += v4.x + v5.x + v6.x + v7.x;
        a0.y += v0.y + v1.y + v2.y + v3.y;  a1.y += v4.y + v5.y + v6.y + v7.y;
        a0.z += v0.z + v1.z + v2.z + v3.z;  a1.z += v4.z + v5.z + v6.z + v7.z;
        a0.w += v0.w + v1.w + v2.w + v3.w;  a1.w += v4.w + v5.w + v6.w + v7.w;
    }
    if (j + 4 <= end) {                                // unroll-4 tier
        int4 ia = row4[j >> 2];
        float4 v0 = f4[ia.x*4 + lane], v1 = f4[ia.y*4 + lane];
        float4 v2 = f4[ia.z*4 + lane], v3 = f4[ia.w*4 + lane];
        a0.x += v0.x + v1.x;  a1.x += v2.x + v3.x;
        a0.y += v0.y + v1.y;  a1.y += v2.y + v3.y;
        a0.z += v0.z + v1.z;  a1.z += v2.z + v3.z;
        a0.w += v0.w + v1.w;  a1.w += v2.w + v3.w;
        j += 4;
    }
    const int* row = reinterpret_cast<const int*>(row4);
    for (; j < end; j++) {                             // scalar tail (<=3)
        int s = row[j];
        float4 v = f4[s*4 + lane];
        a0.x += v.x; a0.y += v.y; a0.z += v.z; a0.w += v.w;
    }
    float4 sv = f4[node*4 + lane];                     // self (pre-scaled)
    float dd = g_dinv[node];
    return make_float4(dd*(a0.x + a1.x + sv.x), dd*(a0.y + a1.y + sv.y),
                       dd*(a0.z + a1.z + sv.z), dd*(a0.w + a1.w + sv.w));
}

// ---------------------------------------------------------------- K2: layer-1 pull + relu + @W2, prescaled out
__global__ void k_pull1(const float* __restrict__ b1,
                        const float* __restrict__ W2, int N) {
    __shared__ float sW2[256];
    __shared__ float sb1[16];
    if (threadIdx.x < 256) sW2[threadIdx.x] = W2[threadIdx.x];
    if (threadIdx.x < 16)  sb1[threadIdx.x] = b1[threadIdx.x];
    __syncthreads();
    int t = blockIdx.x * 256 + threadIdx.x;
    int node = t >> 2;
    bool valid = node < N;
    int nodec = valid ? node : N - 1;                  // keep shfl groups intact
    int lane = t & 3;
    float4 r = pull_node(nodec, lane, (const float4*)g_sfeat);
    float4 h;
    h.x = fmaxf(r.x + sb1[lane*4+0], 0.f);
    h.y = fmaxf(r.y + sb1[lane*4+1], 0.f);
    h.z = fmaxf(r.z + sb1[lane*4+2], 0.f);
    h.w = fmaxf(r.w + sb1[lane*4+3], 0.f);
    float4 res = make_float4(0.f, 0.f, 0.f, 0.f);
    int fb = lane * 4;
#pragma unroll
    for (int g = 0; g < 4; g++) {
        float hx = __shfl_sync(0xffffffffu, h.x, g, 4);
        float hy = __shfl_sync(0xffffffffu, h.y, g, 4);
        float hz = __shfl_sync(0xffffffffu, h.z, g, 4);
        float hw = __shfl_sync(0xffffffffu, h.w, g, 4);
        int kb = g * 4;
        const float* w0 = &sW2[(kb+0)*16 + fb];
        const float* w1 = &sW2[(kb+1)*16 + fb];
        const float* w2 = &sW2[(kb+2)*16 + fb];
        const float* w3 = &sW2[(kb+3)*16 + fb];
        res.x += hx*w0[0] + hy*w1[0] + hz*w2[0] + hw*w3[0];
        res.y += hx*w0[1] + hy*w1[1] + hz*w2[1] + hw*w3[1];
        res.z += hx*w0[2] + hy*w1[2] + hz*w2[2] + hw*w3[2];
        res.w += hx*w0[3] + hy*w1[3] + hz*w2[3] + hw*w3[3];
    }
    if (valid) {
        float dd = g_dinv[node];                       // prescale for layer-2 pull
        res.x *= dd; res.y *= dd; res.z *= dd; res.w *= dd;
        ((float4*)g_acc)[node*4 + lane] = res;
    }
}

// ---------------------------------------------------------------- K3: layer-2 pull + relu + warp-agg pool + out
__global__ void k_pull2(const int* __restrict__ batch,
                        const float* __restrict__ b2,
                        float* __restrict__ out, int N, int G, int nblk) {
    __shared__ int amLast;
    int t = blockIdx.x * 256 + threadIdx.x;
    int node = t >> 2;
    int lane = t & 3;
    float hx = 0.f, hy = 0.f, hz = 0.f, hw = 0.f;
    int g = -1;
    if (node < N) {
        int gb = batch[node];                          // hoisted: overlaps pull latency
        if ((unsigned)gb < (unsigned)G) g = gb;
        float4 r = pull_node(node, lane, (const float4*)g_acc);
        if (lane == 0) g_pos[node] = 0;                // reset for next run (after last read)
        float4 bv = __ldg(&((const float4*)b2)[lane]);
        hx = fmaxf(r.x + bv.x, 0.f);
        hy = fmaxf(r.y + bv.y, 0.f);
        hz = fmaxf(r.z + bv.z, 0.f);
        hw = fmaxf(r.w + bv.w, 0.f);
    }
    // batch is sorted: the warp's 8 nodes almost always share one graph.
    unsigned mask = 0xffffffffu;
    int g0 = __shfl_sync(mask, g, 0);
    bool uniform = __all_sync(mask, g == g0) && (g0 >= 0);
    if (uniform) {
        // reduce across the 8 node-groups (stride-4 lanes keep feature class)
#pragma unroll
        for (int off = 16; off >= 4; off >>= 1) {
            hx += __shfl_down_sync(mask, hx, off);
            hy += __shfl_down_sync(mask, hy, off);
            hz += __shfl_down_sync(mask, hz, off);
            hw += __shfl_down_sync(mask, hw, off);
        }
        int lid = threadIdx.x & 31;
        if (lid < 4) {
            float* p = &g_pool[g0 * 16 + lid * 4];
            atomicAdd(p + 0, hx);
            atomicAdd(p + 1, hy);
            atomicAdd(p + 2, hz);
            atomicAdd(p + 3, hw);
            if (lid == 0) atomicAdd(&g_cnt[g0], 8.0f);
        }
    } else if (g >= 0) {
        float* p = &g_pool[g * 16 + lane * 4];
        atomicAdd(p + 0, hx);
        atomicAdd(p + 1, hy);
        atomicAdd(p + 2, hz);
        atomicAdd(p + 3, hw);
        if (lane == 0) atomicAdd(&g_cnt[g], 1.0f);
    }
    __syncthreads();
    if (threadIdx.x == 0) {
        __threadfence();
        int old = atomicAdd(&g_semaP, 1);
        amLast = (old == nblk - 1);
    }
    __syncthreads();
    if (amLast) {
        __threadfence();
        for (int u = threadIdx.x; u < G * 16; u += 256)
            out[u] = g_pool[u] / fmaxf(g_cnt[u >> 4], 1.0f);
        if (threadIdx.x == 0) g_semaP = 0;             // reset for next run
    }
}

// ----------------------------------------------------------------
extern "C" void kernel_launch(void* const* d_in, const int* in_sizes, int n_in,
                              void* d_out, int out_size) {
    const float* x     = (const float*)d_in[0];
    const int*   ei    = (const int*)d_in[1];
    const int*   batch = (const int*)d_in[2];
    const float* W1    = (const float*)d_in[3];
    const float* b1    = (const float*)d_in[4];
    const float* W2    = (const float*)d_in[5];
    const float* b2    = (const float*)d_in[6];
    float*       out   = (float*)d_out;

    int N = in_sizes[0] / 5;        // 100000
    int E = in_sizes[1] / 2;        // 3200000
    int G = out_size / 16;          // 512

    const int* src = ei;
    const int* dst = ei + E;

    int gN16 = (N * 16 + 255) / 256;           // 6250 init blocks
    int gE4  = ((E + 3) / 4 + 255) / 256;      // 3125 scatter blocks
    int gN4  = (N * 4 + 255) / 256;            // 1563 pull blocks (256 thr)

    k_init_scatter<<<gN16 + gE4, 256>>>(x, W1, src, dst, N, G, E, gN16);
    k_prescale    <<<gN4, 256>>>(N);
    k_pull1       <<<gN4, 256>>>(b1, W2, N);
    k_pull2       <<<gN4, 256>>>(batch, b2, out, N, G, gN4);
}

// round 17
// speedup vs baseline: 1.1650x; 1.0751x over previous
#include <cuda_runtime.h>
#include <cuda_bf16.h>

// GCN 2-layer + mean pool — padded-CSR pull mode; layer-1 aggregates RAW x
// (32B padded rows, 1 L2 sector/gather) and applies W1 post-aggregation.
// Inputs: 0:x[100000,5] f32  1:edge_index[2,3.2M] i32  2:batch[100000] i32 (sorted)
//         3:W1[5,16] 4:b1[16] 5:W2[16,16] 6:b2[16]   Output: [512,16] f32
//
// Layer1: agg_i = dinv_i*(Σ_s dinv_s·x_s + dinv_i·x_i);  h1 = relu(W1ᵀagg + b1)
// Layer2: feat2 = dinv·(h1@W2); standard 16-feat pull; pool.
// Cross-run invariants (graph replay): g_pos zeroed per-node by k_pull2 after its
// last read, g_semaP self-resets, pool/cnt zeroed by k_prescale.

#define MAX_NODES  100000
#define MAX_GRAPHS 512
#define SLOT_LOG   7
#define SLOTS      128          // max in-degree supported (input max ~60)

__device__ float g_dinv[MAX_NODES];
__device__ __align__(16) float g_sx [MAX_NODES * 8];   // dinv*x padded to 8 floats (32B rows)
__device__ __align__(16) float g_acc[MAX_NODES * 16];  // dinv*(h1@W2) (64B rows)
__device__ float g_pool[MAX_GRAPHS * 16];
__device__ float g_cnt [MAX_GRAPHS];
__device__ int   g_pos  [MAX_NODES];          // degree counters (zero across runs)
__device__ __align__(16) int g_eslot[MAX_NODES * SLOTS];  // padded CSR, 51.2 MB
__device__ int   g_semaP;                     // static-zero, self-resetting

// ---------------------------------------------------------------- K0: scatter edges into padded CSR
__global__ void k_scatter(const int* __restrict__ src,
                          const int* __restrict__ dst, int E) {
    int base = (blockIdx.x * 256 + threadIdx.x) * 4;
    if (base + 3 < E) {
        int4 s = *reinterpret_cast<const int4*>(src + base);
        int4 d = *reinterpret_cast<const int4*>(dst + base);
        int p0 = atomicAdd(&g_pos[d.x], 1);
        int p1 = atomicAdd(&g_pos[d.y], 1);
        int p2 = atomicAdd(&g_pos[d.z], 1);
        int p3 = atomicAdd(&g_pos[d.w], 1);
        if (p0 < SLOTS) g_eslot[(d.x << SLOT_LOG) + p0] = s.x;
        if (p1 < SLOTS) g_eslot[(d.y << SLOT_LOG) + p1] = s.y;
        if (p2 < SLOTS) g_eslot[(d.z << SLOT_LOG) + p2] = s.z;
        if (p3 < SLOTS) g_eslot[(d.w << SLOT_LOG) + p3] = s.w;
    } else {
        for (int k = base; k < E; k++) {
            int d = dst[k];
            int p = atomicAdd(&g_pos[d], 1);
            if (p < SLOTS) g_eslot[(d << SLOT_LOG) + p] = src[k];
        }
    }
}

// ---------------------------------------------------------------- K1: dinv + prescaled padded x + zero pool
__global__ void k_prescale(const float* __restrict__ x, int N, int G) {
    int t = blockIdx.x * 256 + threadIdx.x;
    if (t < G * 16) g_pool[t] = 0.f;
    if (t < G)      g_cnt[t]  = 0.f;
    int i = t >> 2;
    if (i >= N) return;
    int lane = t & 3;
    int deg = g_pos[i];
    float di = rsqrtf((float)(deg + 1));               // +1 = self loop
    if (lane == 0) g_dinv[i] = di;
    // lane l holds components 2l, 2l+1 of the 5-feature row (padded with 0)
    int c0 = lane * 2, c1 = lane * 2 + 1;
    float v0 = (c0 < 5) ? __ldg(&x[i * 5 + c0]) * di : 0.f;
    float v1 = (c1 < 5) ? __ldg(&x[i * 5 + c1]) * di : 0.f;
    ((float2*)g_sx)[i * 4 + lane] = make_float2(v0, v1);
}

// ---------------------------------------------------------------- float2 pull core (32B rows): layer 1
__device__ __forceinline__ float2 pull_node2(int node, int lane) {
    const float2* __restrict__ f2 = (const float2*)g_sx;
    const int4* row4 = reinterpret_cast<const int4*>(&g_eslot[node << SLOT_LOG]);
    int end = min(g_pos[node], SLOTS);
    float2 a0 = make_float2(0.f, 0.f);
    float2 a1 = make_float2(0.f, 0.f);
    int j = 0;
    for (; j + 8 <= end; j += 8) {
        int4 ia = row4[(j >> 2) + 0];
        int4 ib = row4[(j >> 2) + 1];
        float2 v0 = f2[ia.x*4 + lane], v1 = f2[ia.y*4 + lane];
        float2 v2 = f2[ia.z*4 + lane], v3 = f2[ia.w*4 + lane];
        float2 v4 = f2[ib.x*4 + lane], v5 = f2[ib.y*4 + lane];
        float2 v6 = f2[ib.z*4 + lane], v7 = f2[ib.w*4 + lane];
        a0.x += v0.x + v1.x + v2.x + v3.x;  a1.x += v4.x + v5.x + v6.x + v7.x;
        a0.y += v0.y + v1.y + v2.y + v3.y;  a1.y += v4.y + v5.y + v6.y + v7.y;
    }
    if (j + 4 <= end) {
        int4 ia = row4[j >> 2];
        float2 v0 = f2[ia.x*4 + lane], v1 = f2[ia.y*4 + lane];
        float2 v2 = f2[ia.z*4 + lane], v3 = f2[ia.w*4 + lane];
        a0.x += v0.x + v1.x;  a1.x += v2.x + v3.x;
        a0.y += v0.y + v1.y;  a1.y += v2.y + v3.y;
        j += 4;
    }
    const int* row = reinterpret_cast<const int*>(row4);
    for (; j < end; j++) {
        float2 v = f2[row[j]*4 + lane];
        a0.x += v.x; a0.y += v.y;
    }
    float2 sv = f2[node*4 + lane];                     // self (pre-scaled)
    float dd = g_dinv[node];
    return make_float2(dd*(a0.x + a1.x + sv.x), dd*(a0.y + a1.y + sv.y));
}

// ---------------------------------------------------------------- float4 pull core (64B rows): layer 2
__device__ __forceinline__ float4 pull_node4(int node, int lane,
                                             const float4* __restrict__ f4) {
    const int4* row4 = reinterpret_cast<const int4*>(&g_eslot[node << SLOT_LOG]);
    int end = min(g_pos[node], SLOTS);
    float4 a0 = make_float4(0.f, 0.f, 0.f, 0.f);
    float4 a1 = make_float4(0.f, 0.f, 0.f, 0.f);
    int j = 0;
    for (; j + 8 <= end; j += 8) {
        int4 ia = row4[(j >> 2) + 0];
        int4 ib = row4[(j >> 2) + 1];
        float4 v0 = f4[ia.x*4 + lane], v1 = f4[ia.y*4 + lane];
        float4 v2 = f4[ia.z*4 + lane], v3 = f4[ia.w*4 + lane];
        float4 v4 = f4[ib.x*4 + lane], v5 = f4[ib.y*4 + lane];
        float4 v6 = f4[ib.z*4 + lane], v7 = f4[ib.w*4 + lane];
        a0.x += v0.x + v1.x + v2.x + v3.x;  a1.x += v4.x + v5.x + v6.x + v7.x;
        a0.y += v0.y + v1.y + v2.y + v3.y;  a1.y += v4.y + v5.y + v6.y + v7.y;
        a0.z += v0.z + v1.z + v2.z + v3.z;  a1.z += v4.z + v5.z + v6.z + v7.z;
        a0.w += v0.w + v1.w + v2.w + v3.w;  a1.w += v4.w + v5.w + v6.w + v7.w;
    }
    if (j + 4 <= end) {
        int4 ia = row4[j >> 2];
        float4 v0 = f4[ia.x*4 + lane], v1 = f4[ia.y*4 + lane];
        float4 v2 = f4[ia.z*4 + lane], v3 = f4[ia.w*4 + lane];
        a0.x += v0.x + v1.x;  a1.x += v2.x + v3.x;
        a0.y += v0.y + v1.y;  a1.y += v2.y + v3.y;
        a0.z += v0.z + v1.z;  a1.z += v2.z + v3.z;
        a0.w += v0.w + v1.w;  a1.w += v2.w + v3.w;
        j += 4;
    }
    const int* row = reinterpret_cast<const int*>(row4);
    for (; j < end; j++) {
        float4 v = f4[row[j]*4 + lane];
        a0.x += v.x; a0.y += v.y; a0.z += v.z; a0.w += v.w;
    }
    float4 sv = f4[node*4 + lane];
    float dd = g_dinv[node];
    return make_float4(dd*(a0.x + a1.x + sv.x), dd*(a0.y + a1.y + sv.y),
                       dd*(a0.z + a1.z + sv.z), dd*(a0.w + a1.w + sv.w));
}

// ---------------------------------------------------------------- K2: layer-1 pull(x) + W1 + relu + @W2 -> g_acc
__global__ void k_pull1(const float* __restrict__ W1,
                        const float* __restrict__ b1,
                        const float* __restrict__ W2, int N) {
    __shared__ float sW1[80];
    __shared__ float sW2[256];
    __shared__ float sb1[16];
    if (threadIdx.x < 80)  sW1[threadIdx.x] = W1[threadIdx.x];
    if (threadIdx.x < 256) sW2[threadIdx.x] = W2[threadIdx.x];
    if (threadIdx.x < 16)  sb1[threadIdx.x] = b1[threadIdx.x];
    __syncthreads();
    int t = blockIdx.x * 256 + threadIdx.x;
    int node = t >> 2;
    bool valid = node < N;
    int nodec = valid ? node : N - 1;                  // keep shfl groups intact
    int lane = t & 3;
    float2 r2 = pull_node2(nodec, lane);
    // collect the node's 5 aggregated components across its 4 lanes
    unsigned m = 0xffffffffu;
    float rx0 = __shfl_sync(m, r2.x, 0, 4);
    float rx1 = __shfl_sync(m, r2.y, 0, 4);
    float rx2 = __shfl_sync(m, r2.x, 1, 4);
    float rx3 = __shfl_sync(m, r2.y, 1, 4);
    float rx4 = __shfl_sync(m, r2.x, 2, 4);
    // h1[f] = relu(sum_k rx_k W1[k][f] + b1[f]), f in [lane*4, lane*4+4)
    int fb = lane * 4;
    float4 h;
    h.x = fmaxf(rx0*sW1[fb+0]    + rx1*sW1[16+fb+0] + rx2*sW1[32+fb+0]
              + rx3*sW1[48+fb+0] + rx4*sW1[64+fb+0] + sb1[fb+0], 0.f);
    h.y = fmaxf(rx0*sW1[fb+1]    + rx1*sW1[16+fb+1] + rx2*sW1[32+fb+1]
              + rx3*sW1[48+fb+1] + rx4*sW1[64+fb+1] + sb1[fb+1], 0.f);
    h.z = fmaxf(rx0*sW1[fb+2]    + rx1*sW1[16+fb+2] + rx2*sW1[32+fb+2]
              + rx3*sW1[48+fb+2] + rx4*sW1[64+fb+2] + sb1[fb+2], 0.f);
    h.w = fmaxf(rx0*sW1[fb+3]    + rx1*sW1[16+fb+3] + rx2*sW1[32+fb+3]
              + rx3*sW1[48+fb+3] + rx4*sW1[64+fb+3] + sb1[fb+3], 0.f);
    // feat2[f] = sum_k h[k] * W2[k][f]  (shfl over the 4-lane group)
    float4 res = make_float4(0.f, 0.f, 0.f, 0.f);
#pragma unroll
    for (int g = 0; g < 4; g++) {
        float hx = __shfl_sync(m, h.x, g, 4);
        float hy = __shfl_sync(m, h.y, g, 4);
        float hz = __shfl_sync(m, h.z, g, 4);
        float hw = __shfl_sync(m, h.w, g, 4);
        int kb = g * 4;
        const float* w0 = &sW2[(kb+0)*16 + fb];
        const float* w1 = &sW2[(kb+1)*16 + fb];
        const float* w2 = &sW2[(kb+2)*16 + fb];
        const float* w3 = &sW2[(kb+3)*16 + fb];
        res.x += hx*w0[0] + hy*w1[0] + hz*w2[0] + hw*w3[0];
        res.y += hx*w0[1] + hy*w1[1] + hz*w2[1] + hw*w3[1];
        res.z += hx*w0[2] + hy*w1[2] + hz*w2[2] + hw*w3[2];
        res.w += hx*w0[3] + hy*w1[3] + hz*w2[3] + hw*w3[3];
    }
    if (valid) {
        float dd = g_dinv[node];                       // prescale for layer-2 pull
        res.x *= dd; res.y *= dd; res.z *= dd; res.w *= dd;
        ((float4*)g_acc)[node*4 + lane] = res;
    }
}

// ---------------------------------------------------------------- K3: layer-2 pull + relu + warp-agg pool + out
__global__ void k_pull2(const int* __restrict__ batch,
                        const float* __restrict__ b2,
                        float* __restrict__ out, int N, int G, int nblk) {
    __shared__ int amLast;
    int t = blockIdx.x * 256 + threadIdx.x;
    int node = t >> 2;
    int lane = t & 3;
    float hx = 0.f, hy = 0.f, hz = 0.f, hw = 0.f;
    int g = -1;
    if (node < N) {
        int gb = batch[node];                          // hoisted: overlaps pull latency
        if ((unsigned)gb < (unsigned)G) g = gb;
        float4 r = pull_node4(node, lane, (const float4*)g_acc);
        if (lane == 0) g_pos[node] = 0;                // reset for next run (after last read)
        float4 bv = __ldg(&((const float4*)b2)[lane]);
        hx = fmaxf(r.x + bv.x, 0.f);
        hy = fmaxf(r.y + bv.y, 0.f);
        hz = fmaxf(r.z + bv.z, 0.f);
        hw = fmaxf(r.w + bv.w, 0.f);
    }
    // batch is sorted: the warp's 8 nodes almost always share one graph.
    unsigned mask = 0xffffffffu;
    int g0 = __shfl_sync(mask, g, 0);
    bool uniform = __all_sync(mask, g == g0) && (g0 >= 0);
    if (uniform) {
#pragma unroll
        for (int off = 16; off >= 4; off >>= 1) {
            hx += __shfl_down_sync(mask, hx, off);
            hy += __shfl_down_sync(mask, hy, off);
            hz += __shfl_down_sync(mask, hz, off);
            hw += __shfl_down_sync(mask, hw, off);
        }
        int lid = threadIdx.x & 31;
        if (lid < 4) {
            float* p = &g_pool[g0 * 16 + lid * 4];
            atomicAdd(p + 0, hx);
            atomicAdd(p + 1, hy);
            atomicAdd(p + 2, hz);
            atomicAdd(p + 3, hw);
            if (lid == 0) atomicAdd(&g_cnt[g0], 8.0f);
        }
    } else if (g >= 0) {
        float* p = &g_pool[g * 16 + lane * 4];
        atomicAdd(p + 0, hx);
        atomicAdd(p + 1, hy);
        atomicAdd(p + 2, hz);
        atomicAdd(p + 3, hw);
        if (lane == 0) atomicAdd(&g_cnt[g], 1.0f);
    }
    __syncthreads();
    if (threadIdx.x == 0) {
        __threadfence();
        int old = atomicAdd(&g_semaP, 1);
        amLast = (old == nblk - 1);
    }
    __syncthreads();
    if (amLast) {
        __threadfence();
        for (int u = threadIdx.x; u < G * 16; u += 256)
            out[u] = g_pool[u] / fmaxf(g_cnt[u >> 4], 1.0f);
        if (threadIdx.x == 0) g_semaP = 0;             // reset for next run
    }
}

// ----------------------------------------------------------------
extern "C" void kernel_launch(void* const* d_in, const int* in_sizes, int n_in,
                              void* d_out, int out_size) {
    const float* x     = (const float*)d_in[0];
    const int*   ei    = (const int*)d_in[1];
    const int*   batch = (const int*)d_in[2];
    const float* W1    = (const float*)d_in[3];
    const float* b1    = (const float*)d_in[4];
    const float* W2    = (const float*)d_in[5];
    const float* b2    = (const float*)d_in[6];
    float*       out   = (float*)d_out;

    int N = in_sizes[0] / 5;        // 100000
    int E = in_sizes[1] / 2;        // 3200000
    int G = out_size / 16;          // 512

    const int* src = ei;
    const int* dst = ei + E;

    int gE4 = ((E + 3) / 4 + 255) / 256;       // 3125 scatter blocks
    int gN4 = (N * 4 + 255) / 256;             // 1563 node blocks (256 thr)

    k_scatter <<<gE4, 256>>>(src, dst, E);
    k_prescale<<<gN4, 256>>>(x, N, G);
    k_pull1   <<<gN4, 256>>>(W1, b1, W2, N);
    k_pull2   <<<gN4, 256>>>(batch, b2, out, N, G, gN4);
}